// round 17
// baseline (speedup 1.0000x reference)
#include <cuda_runtime.h>
#include <cuda_bf16.h>
#include <cstdint>

#define BB 4
#define CC 16
#define KK 16
#define HWHW (512 * 512)          // 262144
#define CHUNK 256                 // pixels per stage -> 1 KB per plane-row
#define NCHUNK (HWHW / CHUNK)     // 1024
#define GRIDX 74                  // 74*4 = 296 blocks = 2/SM, single wave
#define NTH 256
#define KPW 2                     // k's per warp (8 warps x 2 = 16)
#define NSTAGE 3

#define ROW_BYTES (CHUNK * 4)               // 1024 B per (channel|mask) row
#define STAGE_BYTES (2 * CC * ROW_BYTES)    // 32 KB (16 emb + 16 mask rows)
#define SMEM_BYTES (NSTAGE * STAGE_BYTES)   // 96 KB -> 2 blocks/SM

// stats per (b,k): [0..15] channel sums, [16] sum ||e||^2 over fg, [17] count
__device__ float g_stats[BB][KK][18];   // zeroed at load; re-zeroed by last block each launch
__device__ unsigned int g_done;

__device__ __forceinline__ float warp_sum(float x) {
#pragma unroll
    for (int off = 16; off > 0; off >>= 1)
        x += __shfl_down_sync(0xffffffffu, x, off);
    return x;
}
__device__ __forceinline__ uint32_t smem_u32(const void* p) {
    return (uint32_t)__cvta_generic_to_shared(p);
}
__device__ __forceinline__ void mbar_init(uint32_t mbar, uint32_t count) {
    asm volatile("mbarrier.init.shared.b64 [%0], %1;" :: "r"(mbar), "r"(count) : "memory");
}
__device__ __forceinline__ void mbar_expect_tx(uint32_t mbar, uint32_t bytes) {
    asm volatile("mbarrier.arrive.expect_tx.shared.b64 _, [%0], %1;" :: "r"(mbar), "r"(bytes) : "memory");
}
__device__ __forceinline__ void mbar_wait(uint32_t mbar, uint32_t parity) {
    uint32_t done;
    asm volatile(
        "{\n\t.reg .pred p;\n\t"
        "mbarrier.try_wait.parity.acquire.cta.shared::cta.b64 p, [%1], %2;\n\t"
        "selp.b32 %0, 1, 0, p;\n\t}"
        : "=r"(done) : "r"(mbar), "r"(parity) : "memory");
    if (!done) {
        asm volatile(
            "{\n\t.reg .pred P1;\n\t"
            "WAIT_LOOP_%=:\n\t"
            "mbarrier.try_wait.parity.acquire.cta.shared::cta.b64 P1, [%0], %1, 0x989680;\n\t"
            "@P1 bra.uni WAIT_DONE_%=;\n\t"
            "bra.uni WAIT_LOOP_%=;\n\t"
            "WAIT_DONE_%=:\n\t}"
            :: "r"(mbar), "r"(parity) : "memory");
    }
}
__device__ __forceinline__ void bulk_cp(uint32_t dst_smem, const void* src, uint32_t bytes, uint32_t mbar) {
    asm volatile(
        "cp.async.bulk.shared::cta.global.mbarrier::complete_tx::bytes [%0], [%1], %2, [%3];"
        :: "r"(dst_smem), "l"(src), "r"(bytes), "r"(mbar) : "memory");
}

// ---------------- fused kernel: 1KB bulk-async rows + contiguous ranges ----------------
__global__ __launch_bounds__(NTH, 2)
void stats_kernel(const float* __restrict__ emb, const int* __restrict__ mask,
                  float* __restrict__ out) {
    extern __shared__ __align__(16) char smraw[];
    __shared__ __align__(8) unsigned long long full_bar[NSTAGE];

    const int b   = blockIdx.y;
    const int bx  = blockIdx.x;
    const int tid = threadIdx.x;
    const int w   = tid >> 5;
    const int l   = tid & 31;
    const int k0  = w * KPW;

    // contiguous chunk range: every bulk stream advances sequentially 1 KB at a time
    const int ch_begin = (int)(((long long)bx * NCHUNK) / GRIDX);
    const int ch_end   = (int)(((long long)(bx + 1) * NCHUNK) / GRIDX);

    const float* embB = emb  + (size_t)b * CC * HWHW;
    const int*   mskB = mask + (size_t)b * KK * HWHW;

    if (tid == 0) {
#pragma unroll
        for (int s = 0; s < NSTAGE; ++s)
            mbar_init(smem_u32(&full_bar[s]), 1);
    }
    __syncthreads();

    float acc[KPW][CC];
    float ssq[KPW], cnt[KPW];
#pragma unroll
    for (int kk = 0; kk < KPW; ++kk) {
#pragma unroll
        for (int c = 0; c < CC; ++c) acc[kk][c] = 0.0f;
        ssq[kk] = 0.0f; cnt[kk] = 0.0f;
    }

    // single-thread bulk prefetch: 32 ops of 1 KB, tx-counted on the stage mbar
    auto prefetch = [&](int stage, int ch) {
        if (tid == 0 && ch < ch_end) {
            const int pix0 = ch * CHUNK;
            uint32_t se = smem_u32(smraw + stage * STAGE_BYTES);
            uint32_t sk = se + CC * ROW_BYTES;
            uint32_t mb = smem_u32(&full_bar[stage]);
            mbar_expect_tx(mb, STAGE_BYTES);
#pragma unroll
            for (int c = 0; c < CC; ++c)
                bulk_cp(se + c * ROW_BYTES, embB + (size_t)c * HWHW + pix0, ROW_BYTES, mb);
#pragma unroll
            for (int k = 0; k < KK; ++k)
                bulk_cp(sk + k * ROW_BYTES, mskB + (size_t)k * HWHW + pix0, ROW_BYTES, mb);
        }
    };

#pragma unroll
    for (int s = 0; s < NSTAGE - 1; ++s)
        prefetch(s, ch_begin + s);

    int cons = 0, pf = NSTAGE - 1, ph = 0;
    for (int ch = ch_begin; ch < ch_end; ++ch) {
        // all warps passed the previous iteration -> the stage 'pf' (consumed
        // last iteration) is reusable once this barrier completes
        __syncthreads();
        mbar_wait(smem_u32(&full_bar[cons]), ph);

        const float* eb = (const float*)(smraw + cons * STAGE_BYTES);
        const int*   mb = (const int*)(smraw + cons * STAGE_BYTES + CC * ROW_BYTES);

        // 4 sub-iterations cover 256 px; lane owns pixel-pair p = sub*32 + l
#pragma unroll
        for (int sub = 0; sub < 4; ++sub) {
            const int p = sub * 32 + l;

            float mf[KPW][2];
#pragma unroll
            for (int kk = 0; kk < KPW; ++kk) {
                int2 m = ((const int2*)(mb + (k0 + kk) * CHUNK))[p];
                mf[kk][0] = (float)m.x;    // masks are exactly 0/1
                mf[kk][1] = (float)m.y;
            }

            float s2a = 0.0f, s2b = 0.0f;
#pragma unroll
            for (int c = 0; c < CC; ++c) {
                float2 e = ((const float2*)(eb + c * CHUNK))[p];
                s2a = fmaf(e.x, e.x, s2a);
                s2b = fmaf(e.y, e.y, s2b);
#pragma unroll
                for (int kk = 0; kk < KPW; ++kk) {
                    float a = acc[kk][c];
                    a = fmaf(e.x, mf[kk][0], a);
                    a = fmaf(e.y, mf[kk][1], a);
                    acc[kk][c] = a;
                }
            }
#pragma unroll
            for (int kk = 0; kk < KPW; ++kk) {
                float s = ssq[kk];
                s = fmaf(s2a, mf[kk][0], s);
                s = fmaf(s2b, mf[kk][1], s);
                ssq[kk] = s;
                cnt[kk] += mf[kk][0] + mf[kk][1];
            }
        }

        prefetch(pf, ch + NSTAGE - 1);
        if (++cons == NSTAGE) { cons = 0; ph ^= 1; }
        pf = (pf + 1 == NSTAGE) ? 0 : pf + 1;
    }

    // ---- warp reduce + global accumulate ----
#pragma unroll
    for (int kk = 0; kk < KPW; ++kk) {
        const int k = k0 + kk;
#pragma unroll
        for (int c = 0; c < CC; ++c) {
            float v = warp_sum(acc[kk][c]);
            if (l == 0) atomicAdd(&g_stats[b][k][c], v);
        }
        float s = warp_sum(ssq[kk]);
        float n = warp_sum(cnt[kk]);
        if (l == 0) {
            atomicAdd(&g_stats[b][k][16], s);
            atomicAdd(&g_stats[b][k][17], n);
        }
    }

    // ---- last-block epilogue: compute loss, write out, reset globals ----
    __shared__ bool is_last;
    __threadfence();
    __syncthreads();
    if (tid == 0) {
        unsigned int v = atomicAdd(&g_done, 1u);
        is_last = (v == (unsigned int)(BB * GRIDX) - 1u);
    }
    __syncthreads();
    if (!is_last) return;
    __threadfence();

    float* sh_means = (float*)smraw;                      // [BB][KK][CC] = 1024 floats
    float* sh_pull  = sh_means + BB * KK * CC;
    float* sh_valid = sh_pull + BB * KK;
    float* sh_push  = sh_valid + BB * KK;
    float* sh_pullb = sh_push + BB;
    float* sh_M     = sh_pullb + BB;

    const int t = tid;
    if (t < BB) sh_push[t] = 0.0f;

    if (t < BB * KK) {
        int bb = t >> 4, k = t & 15;
        volatile float* s = g_stats[bb][k];
        float cntv = s[17];
        float ssqv = s[16];
        bool valid = cntv > 0.0f;
        float inv = 1.0f / fmaxf(cntv, 1.0f);
        float dot = 0.0f;
#pragma unroll
        for (int c = 0; c < CC; ++c) {
            float sv = s[c];
            float m = sv * inv;
            sh_means[(bb * KK + k) * CC + c] = m;
            dot = fmaf(sv, m, dot);
        }
        sh_pull[bb * KK + k]  = valid ? (ssqv - dot) / (cntv + 1e-6f) : 0.0f;
        sh_valid[bb * KK + k] = valid ? 1.0f : 0.0f;
    }
    __syncthreads();

    for (int q = t; q < BB * KK * 18; q += NTH)
        ((float*)g_stats)[q] = 0.0f;
    if (t == 0) g_done = 0u;

    if (t < BB) {
        float M = 0.0f, ps = 0.0f;
        for (int k = 0; k < KK; ++k) { M += sh_valid[t * KK + k]; ps += sh_pull[t * KK + k]; }
        sh_M[t]     = M;
        sh_pullb[t] = ps / fmaxf(M, 1.0f);
    }

    float local[BB] = {0.0f, 0.0f, 0.0f, 0.0f};
    for (int idx = t; idx < BB * KK * KK; idx += NTH) {
        int bb = idx >> 8;
        int ij = idx & 255;
        int ii = ij >> 4, jj = ij & 15;
        if (ii < jj && sh_valid[bb * KK + ii] > 0.0f && sh_valid[bb * KK + jj] > 0.0f) {
            float d2 = 0.0f;
#pragma unroll
            for (int c = 0; c < CC; ++c) {
                float d = sh_means[(bb * KK + ii) * CC + c] - sh_means[(bb * KK + jj) * CC + c];
                d2 = fmaf(d, d, d2);
            }
            float dist = sqrtf(d2 + 1e-12f);
            float tm = fmaxf(1.5f - dist, 0.0f);
            local[bb] += tm * tm;
        }
    }
#pragma unroll
    for (int bb = 0; bb < BB; ++bb)
        if (local[bb] != 0.0f) atomicAdd(&sh_push[bb], local[bb]);
    __syncthreads();

    if (t == 0) {
        float loss = 0.0f;
        for (int bb = 0; bb < BB; ++bb) {
            float M = sh_M[bb];
            float npairs = M * (M - 1.0f) * 0.5f;
            float push = (M > 1.0f) ? sh_push[bb] / fmaxf(npairs, 1.0f) : 0.0f;
            loss += 0.5f * sh_pullb[bb] + push;   // DELTA_PULL = 0.5
        }
        out[0] = loss * (1.0f / BB);
    }
}

extern "C" void kernel_launch(void* const* d_in, const int* in_sizes, int n_in,
                              void* d_out, int out_size) {
    const float* emb  = (const float*)d_in[0];
    const int*   mask = (const int*)d_in[1];
    float* out = (float*)d_out;

    cudaFuncSetAttribute(stats_kernel, cudaFuncAttributeMaxDynamicSharedMemorySize, SMEM_BYTES);

    dim3 grid(GRIDX, BB);
    stats_kernel<<<grid, NTH, SMEM_BYTES>>>(emb, mask, out);
}